// round 2
// baseline (speedup 1.0000x reference)
#include <cuda_runtime.h>
#include <cstdint>
#include <cstddef>

// ---------------------------------------------------------------------------
// Problem constants (fixed by setup_inputs)
// ---------------------------------------------------------------------------
constexpr int B  = 4;
constexpr int N  = 16384;
constexpr int C  = 16;
constexpr int S  = 1024;       // npoint
constexpr int NS = 64;         // NSAMPLE
constexpr int NG = B * S;                 // 4096 groups
constexpr int M  = NG * NS;               // 262144 columns
constexpr int CIN1 = 3 + C;               // 19
constexpr int GB = M / 128;               // 2048 gemm blocks

// Output layout: new_xyz (B,S,3) | new_features (B,128,S) | inds (B,S), all f32
constexpr int OUT_FEAT = B * S * 3;            // 12288
constexpr int OUT_INDS = OUT_FEAT + B * 128 * S; // 536576
// total = 540672

// ---------------------------------------------------------------------------
// Scratch (device globals; no runtime allocation allowed)
// ---------------------------------------------------------------------------
__device__ float g_newxyz[NG * 3];
__device__ int   g_idx[NG * NS];
__device__ float g_X0[(size_t)CIN1 * M];     // ~20 MB
__device__ float g_Y1[(size_t)64 * M];       // 67 MB
__device__ float g_Y2[(size_t)64 * M];       // 67 MB
__device__ float g_max3[(size_t)128 * NG];   // 2 MB
__device__ float g_part[(size_t)128 * GB * 2]; // deterministic BN partials
__device__ float g_scl1[64],  g_shf1[64];
__device__ float g_scl2[64],  g_shf2[64];
__device__ float g_scl3[128], g_shf3[128];

// ---------------------------------------------------------------------------
// 1) Furthest point sampling: one CTA per batch, 1024 threads, 16 pts/thread.
//    x,y,dist register-resident; z in dynamic smem (reg budget: 64/thread).
//    Arithmetic matches reference: (dx*dx + dy*dy) + dz*dz, no FMA fusion.
// ---------------------------------------------------------------------------
__global__ void __launch_bounds__(1024, 1)
fps_kernel(const float* __restrict__ xyz, float* __restrict__ out)
{
    extern __shared__ float sz[];     // N floats (64 KB)
    __shared__ float rv[32];
    __shared__ int   ri[32];
    __shared__ int   sfar;

    const int b = blockIdx.x;
    const float* __restrict__ p = xyz + (size_t)b * N * 3;
    const int t = threadIdx.x;
    const int lane = t & 31, wid = t >> 5;

    float X[16], Y[16], D[16];
#pragma unroll
    for (int k = 0; k < 16; k++) {
        int j = t + (k << 10);
        X[k]  = p[3 * j];
        Y[k]  = p[3 * j + 1];
        sz[j] = p[3 * j + 2];
        D[k]  = 1e10f;
    }
    __syncthreads();

    int far = 0;
    for (int i = 0; i < S; i++) {
        float cx = p[3 * far], cy = p[3 * far + 1], cz = p[3 * far + 2];
        if (t == 0) {
            int gi = b * S + i;
            g_newxyz[3 * gi]     = cx;
            g_newxyz[3 * gi + 1] = cy;
            g_newxyz[3 * gi + 2] = cz;
            out[3 * gi]     = cx;
            out[3 * gi + 1] = cy;
            out[3 * gi + 2] = cz;
            out[OUT_INDS + gi] = (float)far;
        }
        float best = -1.0f;
        int bk = 0;
#pragma unroll
        for (int k = 0; k < 16; k++) {
            int j = t + (k << 10);
            float dx = __fadd_rn(X[k],  -cx);
            float dy = __fadd_rn(Y[k],  -cy);
            float dz = __fadd_rn(sz[j], -cz);
            float d  = __fadd_rn(__fadd_rn(__fmul_rn(dx, dx), __fmul_rn(dy, dy)),
                                 __fmul_rn(dz, dz));
            float nd = fminf(D[k], d);
            D[k] = nd;
            if (nd > best) { best = nd; bk = k; }
        }
        int bi = t + (bk << 10);
#pragma unroll
        for (int o = 16; o > 0; o >>= 1) {
            float ov = __shfl_xor_sync(0xffffffffu, best, o);
            int   oi = __shfl_xor_sync(0xffffffffu, bi,   o);
            if (ov > best || (ov == best && oi < bi)) { best = ov; bi = oi; }
        }
        if (lane == 0) { rv[wid] = best; ri[wid] = bi; }
        __syncthreads();
        if (wid == 0) {
            best = rv[lane]; bi = ri[lane];
#pragma unroll
            for (int o = 16; o > 0; o >>= 1) {
                float ov = __shfl_xor_sync(0xffffffffu, best, o);
                int   oi = __shfl_xor_sync(0xffffffffu, bi,   o);
                if (ov > best || (ov == best && oi < bi)) { best = ov; bi = oi; }
            }
            if (lane == 0) sfar = bi;
        }
        __syncthreads();
        far = sfar;
    }
}

// ---------------------------------------------------------------------------
// 2) Ball query: one warp per center, ordered first-NS collection via ballot.
// ---------------------------------------------------------------------------
__global__ void ball_kernel(const float* __restrict__ xyz)
{
    int gw = (blockIdx.x * blockDim.x + threadIdx.x) >> 5;
    if (gw >= NG) return;
    int lane = threadIdx.x & 31;
    int b = gw >> 10;   // / S
    const float* __restrict__ p = xyz + (size_t)b * N * 3;
    float cx = g_newxyz[3 * gw], cy = g_newxyz[3 * gw + 1], cz = g_newxyz[3 * gw + 2];
    int* outp = g_idx + gw * NS;

    int cnt = 0, first = 0;
    for (int base = 0; base < N; base += 32) {
        int j = base + lane;
        float dx = __fadd_rn(p[3 * j],     -cx);
        float dy = __fadd_rn(p[3 * j + 1], -cy);
        float dz = __fadd_rn(p[3 * j + 2], -cz);
        float d  = __fadd_rn(__fadd_rn(__fmul_rn(dx, dx), __fmul_rn(dy, dy)),
                             __fmul_rn(dz, dz));
        bool hit = d < 0.16f;
        unsigned mask = __ballot_sync(0xffffffffu, hit);
        if (mask) {
            if (cnt == 0) first = base + __ffs(mask) - 1;
            int pos = cnt + __popc(mask & ((1u << lane) - 1u));
            if (hit && pos < NS) outp[pos] = j;
            cnt += __popc(mask);
            if (cnt >= NS) break;
        }
    }
    for (int q = cnt + lane; q < NS; q += 32) outp[q] = first;
}

// ---------------------------------------------------------------------------
// 3) Grouping: build X0 [19][M] (normalized xyz + gathered features)
// ---------------------------------------------------------------------------
__global__ void group_kernel(const float* __restrict__ xyz,
                             const float* __restrict__ feat)
{
    int m = blockIdx.x * blockDim.x + threadIdx.x;
    if (m >= M) return;
    int g = m >> 6;     // / NS
    int b = g >> 10;    // / S
    int j = g_idx[m];
    const float* p = xyz + ((size_t)b * N + j) * 3;
    float cx = g_newxyz[3 * g], cy = g_newxyz[3 * g + 1], cz = g_newxyz[3 * g + 2];
    g_X0[(size_t)0 * M + m] = (p[0] - cx) * 2.5f;
    g_X0[(size_t)1 * M + m] = (p[1] - cy) * 2.5f;
    g_X0[(size_t)2 * M + m] = (p[2] - cz) * 2.5f;
    const float* fb = feat + (size_t)b * C * N + j;
#pragma unroll
    for (int c = 0; c < C; c++)
        g_X0[(size_t)(3 + c) * M + m] = fb[(size_t)c * N];
}

// ---------------------------------------------------------------------------
// 4) 64-output tiled SGEMM with fused input-BN+ReLU, BN partial stats,
//    and (layer 3) fused per-group max.  LAYER selects scratch tensors.
// ---------------------------------------------------------------------------
template<int CIN, int LAYER>
__global__ void __launch_bounds__(256)
gemm64_kernel(const float* __restrict__ Wg, int obase)
{
    constexpr bool NORM   = (LAYER != 1);
    constexpr bool STOREY = (LAYER != 3);
    constexpr bool DOMAX  = (LAYER == 3);

    const float* __restrict__ Xin =
        (LAYER == 1) ? g_X0 : (LAYER == 2) ? g_Y1 : g_Y2;
    const float* __restrict__ scl = (LAYER == 2) ? g_scl1 : g_scl2;
    const float* __restrict__ shf = (LAYER == 2) ? g_shf1 : g_shf2;
    float* __restrict__ Yout = (LAYER == 1) ? g_Y1 : g_Y2;

    __shared__ float Ws[CIN * 64];
    __shared__ float Xs[32 * 128];

    const int tid = threadIdx.x;
    const int m0  = blockIdx.x * 128;
    const int tx  = tid & 15, ty = tid >> 4;

    for (int i = tid; i < CIN * 64; i += 256) {
        int c = i >> 6, o = i & 63;
        Ws[i] = Wg[o * CIN + c];
    }

    float acc[4][8];
#pragma unroll
    for (int i = 0; i < 4; i++)
#pragma unroll
        for (int jj = 0; jj < 8; jj++) acc[i][jj] = 0.f;

    for (int k0 = 0; k0 < CIN; k0 += 32) {
        const int kn = (CIN - k0) < 32 ? (CIN - k0) : 32;
        __syncthreads();
        for (int i = tid; i < kn * 32; i += 256) {
            int r = i >> 5, c4 = i & 31;
            float4 v = *reinterpret_cast<const float4*>(
                Xin + (size_t)(k0 + r) * M + m0 + c4 * 4);
            if (NORM) {
                float sc = scl[k0 + r], sh = shf[k0 + r];
                v.x = fmaxf(fmaf(v.x, sc, sh), 0.f);
                v.y = fmaxf(fmaf(v.y, sc, sh), 0.f);
                v.z = fmaxf(fmaf(v.z, sc, sh), 0.f);
                v.w = fmaxf(fmaf(v.w, sc, sh), 0.f);
            }
            *reinterpret_cast<float4*>(Xs + r * 128 + c4 * 4) = v;
        }
        __syncthreads();
#pragma unroll 4
        for (int k = 0; k < kn; k++) {
            float4 w4 = *reinterpret_cast<const float4*>(Ws + (k0 + k) * 64 + ty * 4);
            float4 xa = *reinterpret_cast<const float4*>(Xs + k * 128 + tx * 8);
            float4 xb = *reinterpret_cast<const float4*>(Xs + k * 128 + tx * 8 + 4);
            float wr[4] = {w4.x, w4.y, w4.z, w4.w};
            float xr[8] = {xa.x, xa.y, xa.z, xa.w, xb.x, xb.y, xb.z, xb.w};
#pragma unroll
            for (int i = 0; i < 4; i++)
#pragma unroll
                for (int jj = 0; jj < 8; jj++)
                    acc[i][jj] = fmaf(wr[i], xr[jj], acc[i][jj]);
        }
    }

    if (STOREY) {
#pragma unroll
        for (int i = 0; i < 4; i++) {
            size_t off = (size_t)(ty * 4 + i) * M + m0 + tx * 8;
            float4 a = make_float4(acc[i][0], acc[i][1], acc[i][2], acc[i][3]);
            float4 q = make_float4(acc[i][4], acc[i][5], acc[i][6], acc[i][7]);
            *reinterpret_cast<float4*>(Yout + off)     = a;
            *reinterpret_cast<float4*>(Yout + off + 4) = q;
        }
    }

    // per-channel partial sum / sumsq (deterministic: fixed shfl order, no atomics)
#pragma unroll
    for (int i = 0; i < 4; i++) {
        float sm = 0.f, sq = 0.f;
#pragma unroll
        for (int jj = 0; jj < 8; jj++) {
            sm += acc[i][jj];
            sq += acc[i][jj] * acc[i][jj];
        }
#pragma unroll
        for (int o = 8; o > 0; o >>= 1) {
            sm += __shfl_xor_sync(0xffffffffu, sm, o);
            sq += __shfl_xor_sync(0xffffffffu, sq, o);
        }
        if (tx == 0) {
            int o = obase + ty * 4 + i;
            g_part[((size_t)o * GB + blockIdx.x) * 2]     = sm;
            g_part[((size_t)o * GB + blockIdx.x) * 2 + 1] = sq;
        }
    }

    if (DOMAX) {
#pragma unroll
        for (int i = 0; i < 4; i++) {
            float mx = acc[i][0];
#pragma unroll
            for (int jj = 1; jj < 8; jj++) mx = fmaxf(mx, acc[i][jj]);
#pragma unroll
            for (int o = 4; o > 0; o >>= 1)
                mx = fmaxf(mx, __shfl_xor_sync(0xffffffffu, mx, o));
            if ((tx & 7) == 0) {
                int grp = (m0 >> 6) + (tx >> 3);
                g_max3[(size_t)(obase + ty * 4 + i) * NG + grp] = mx;
            }
        }
    }
}

// ---------------------------------------------------------------------------
// 5) BN stat finalize (deterministic fixed-order reduction over GB partials)
// ---------------------------------------------------------------------------
template<int LAYER, int COUT>
__global__ void fin_kernel(const float* __restrict__ gam,
                           const float* __restrict__ bet)
{
    float* scl = (LAYER == 1) ? g_scl1 : (LAYER == 2) ? g_scl2 : g_scl3;
    float* shf = (LAYER == 1) ? g_shf1 : (LAYER == 2) ? g_shf2 : g_shf3;
    int o = threadIdx.x;
    if (o >= COUT) return;
    float sm = 0.f, sq = 0.f;
    const float* pp = g_part + (size_t)o * GB * 2;
    for (int i = 0; i < GB; i++) { sm += pp[2 * i]; sq += pp[2 * i + 1]; }
    float mean = sm * (1.0f / (float)M);
    float var  = sq * (1.0f / (float)M) - mean * mean;
    float sc = gam[o] * rsqrtf(var + 1e-5f);
    scl[o] = sc;
    shf[o] = fmaf(-mean, sc, bet[o]);
}

// ---------------------------------------------------------------------------
// 6) Final: normalize+ReLU the group-max, write new_features
// ---------------------------------------------------------------------------
__global__ void out_feat_kernel(float* __restrict__ out)
{
    int idx = blockIdx.x * blockDim.x + threadIdx.x;
    if (idx >= 128 * NG) return;
    int o = idx >> 12;        // / NG
    int g = idx & (NG - 1);
    int b = g >> 10, s = g & 1023;
    float v = fmaxf(fmaf(g_max3[idx], g_scl3[o], g_shf3[o]), 0.f);
    out[OUT_FEAT + ((size_t)(b * 128 + o)) * S + s] = v;
}

// ---------------------------------------------------------------------------
// Launch
// ---------------------------------------------------------------------------
extern "C" void kernel_launch(void* const* d_in, const int* in_sizes, int n_in,
                              void* d_out, int out_size)
{
    (void)in_sizes; (void)n_in; (void)out_size;
    const float* xyz  = (const float*)d_in[0];
    const float* feat = (const float*)d_in[1];
    const float* W1   = (const float*)d_in[2];
    const float* g1   = (const float*)d_in[3];
    const float* b1   = (const float*)d_in[4];
    const float* W2   = (const float*)d_in[5];
    const float* g2   = (const float*)d_in[6];
    const float* b2   = (const float*)d_in[7];
    const float* W3   = (const float*)d_in[8];
    const float* g3   = (const float*)d_in[9];
    const float* b3   = (const float*)d_in[10];
    float* out = (float*)d_out;

    cudaFuncSetAttribute(fps_kernel,
                         cudaFuncAttributeMaxDynamicSharedMemorySize, N * 4);

    fps_kernel<<<B, 1024, N * 4>>>(xyz, out);
    ball_kernel<<<(NG * 32) / 256, 256>>>(xyz);
    group_kernel<<<M / 256, 256>>>(xyz, feat);

    gemm64_kernel<CIN1, 1><<<GB, 256>>>(W1, 0);
    fin_kernel<1, 64><<<1, 64>>>(g1, b1);

    gemm64_kernel<64, 2><<<GB, 256>>>(W2, 0);
    fin_kernel<2, 64><<<1, 64>>>(g2, b2);

    gemm64_kernel<64, 3><<<GB, 256>>>(W3, 0);
    gemm64_kernel<64, 3><<<GB, 256>>>(W3 + 64 * 64, 64);
    fin_kernel<3, 128><<<1, 128>>>(g3, b3);

    out_feat_kernel<<<(128 * NG) / 256, 256>>>(out);
}

// round 3
// speedup vs baseline: 1.3481x; 1.3481x over previous
#include <cuda_runtime.h>
#include <cooperative_groups.h>
#include <cstdint>
#include <cstddef>

namespace cg = cooperative_groups;

// ---------------------------------------------------------------------------
// Problem constants (fixed by setup_inputs)
// ---------------------------------------------------------------------------
constexpr int B  = 4;
constexpr int N  = 16384;
constexpr int C  = 16;
constexpr int S  = 1024;       // npoint
constexpr int NS = 64;         // NSAMPLE
constexpr int NG = B * S;                 // 4096 groups
constexpr int M  = NG * NS;               // 262144 columns
constexpr int CIN1 = 3 + C;               // 19
constexpr int GB = M / 128;               // 2048 gemm blocks

// FPS cluster decomposition
constexpr int CL      = 8;                // CTAs per cluster (one cluster per batch)
constexpr int FPS_T   = 256;              // threads per CTA
constexpr int PPT     = N / CL / FPS_T;   // 8 points per thread
constexpr int SLICE   = N / CL;           // 2048 points per CTA

// Output layout: new_xyz (B,S,3) | new_features (B,128,S) | inds (B,S), all f32
constexpr int OUT_FEAT = B * S * 3;              // 12288
constexpr int OUT_INDS = OUT_FEAT + B * 128 * S; // 536576

// ---------------------------------------------------------------------------
// Scratch (device globals; no runtime allocation allowed)
// ---------------------------------------------------------------------------
__device__ float g_newxyz[NG * 3];
__device__ int   g_idx[NG * NS];
__device__ float g_X0[(size_t)CIN1 * M];     // ~20 MB
__device__ float g_Y1[(size_t)64 * M];       // 67 MB
__device__ float g_Y2[(size_t)64 * M];       // 67 MB
__device__ float g_max3[(size_t)128 * NG];   // 2 MB
__device__ float g_part[(size_t)128 * GB * 2]; // deterministic BN partials
__device__ float g_scl1[64],  g_shf1[64];
__device__ float g_scl2[64],  g_shf2[64];
__device__ float g_scl3[128], g_shf3[128];

// ---------------------------------------------------------------------------
// 1) Furthest point sampling — 8-CTA cluster per batch.
//    Each CTA owns a 2048-point slice register-resident (x,y,z,dist).
//    Argmax via u64 keys (dist_bits<<32 | (N-1-idx)): max == argmax with
//    first-occurrence tie-break, matching jnp.argmax exactly.
//    Distance arithmetic identical to the passing R2 kernel (no FMA fusion).
// ---------------------------------------------------------------------------
__global__ void __launch_bounds__(FPS_T, 1) __cluster_dims__(CL, 1, 1)
fps_kernel(const float* __restrict__ xyz, float* __restrict__ out)
{
    __shared__ unsigned long long wkeys[FPS_T / 32];
    __shared__ unsigned long long bkey;
    __shared__ unsigned long long slots[2][CL];

    cg::cluster_group cluster = cg::this_cluster();
    const unsigned rank = cluster.block_rank();
    const int b = blockIdx.x / CL;
    const float* __restrict__ p = xyz + (size_t)b * N * 3;
    const int t = threadIdx.x;
    const int lane = t & 31, wid = t >> 5;
    const int jbase = rank * SLICE + t;     // + k*FPS_T

    float X[PPT], Y[PPT], Z[PPT], D[PPT];
#pragma unroll
    for (int k = 0; k < PPT; k++) {
        int j = jbase + k * FPS_T;
        X[k] = p[3 * j];
        Y[k] = p[3 * j + 1];
        Z[k] = p[3 * j + 2];
        D[k] = 1e10f;
    }

    int far = 0;
    for (int i = 0; i < S; i++) {
        // outputs for this iteration's centroid (deterministic: rank0/t0 only)
        float cx = p[3 * far], cy = p[3 * far + 1], cz = p[3 * far + 2];
        if (rank == 0 && t == 0) {
            int gi = b * S + i;
            g_newxyz[3 * gi]     = cx;
            g_newxyz[3 * gi + 1] = cy;
            g_newxyz[3 * gi + 2] = cz;
            out[3 * gi]     = cx;
            out[3 * gi + 1] = cy;
            out[3 * gi + 2] = cz;
            out[OUT_INDS + gi] = (float)far;
        }

        // distance update + local best (value,slot) — exact reference arithmetic
        float best = -1.0f;
        int bk = 0;
#pragma unroll
        for (int k = 0; k < PPT; k++) {
            float dx = __fadd_rn(X[k], -cx);
            float dy = __fadd_rn(Y[k], -cy);
            float dz = __fadd_rn(Z[k], -cz);
            float d  = __fadd_rn(__fadd_rn(__fmul_rn(dx, dx), __fmul_rn(dy, dy)),
                                 __fmul_rn(dz, dz));
            float nd = fminf(D[k], d);
            D[k] = nd;
            if (nd > best) { best = nd; bk = k; }
        }
        int bi = jbase + bk * FPS_T;   // global-within-batch index
        unsigned long long key =
            ((unsigned long long)__float_as_uint(best) << 32) |
            (unsigned)(N - 1 - bi);

        // warp max
#pragma unroll
        for (int o = 16; o > 0; o >>= 1) {
            unsigned long long ok = __shfl_xor_sync(0xffffffffu, key, o);
            if (ok > key) key = ok;
        }
        if (lane == 0) wkeys[wid] = key;
        __syncthreads();
        if (wid == 0) {
            key = wkeys[lane & (FPS_T / 32 - 1)];
#pragma unroll
            for (int o = (FPS_T / 64); o > 0; o >>= 1) {
                unsigned long long ok = __shfl_xor_sync(0xffffffffu, key, o);
                if (ok > key) key = ok;
            }
            if (lane == 0) bkey = key;
        }
        __syncthreads();

        // push block winner into slot[rank] of every cluster CTA (incl. self)
        int par = i & 1;
        if (t < CL) {
            unsigned long long* dst = (unsigned long long*)
                cluster.map_shared_rank((void*)&slots[par][rank], t);
            *dst = bkey;
        }
        cluster.sync();

        // every thread resolves cluster argmax locally
        unsigned long long mk = slots[par][0];
#pragma unroll
        for (int r = 1; r < CL; r++) {
            unsigned long long ok = slots[par][r];
            if (ok > mk) mk = ok;
        }
        far = N - 1 - (int)(mk & 0xffffffffu);
    }
}

// ---------------------------------------------------------------------------
// 2) Ball query: one warp per center, ordered first-NS collection via ballot.
// ---------------------------------------------------------------------------
__global__ void ball_kernel(const float* __restrict__ xyz)
{
    int gw = (blockIdx.x * blockDim.x + threadIdx.x) >> 5;
    if (gw >= NG) return;
    int lane = threadIdx.x & 31;
    int b = gw >> 10;   // / S
    const float* __restrict__ p = xyz + (size_t)b * N * 3;
    float cx = g_newxyz[3 * gw], cy = g_newxyz[3 * gw + 1], cz = g_newxyz[3 * gw + 2];
    int* outp = g_idx + gw * NS;

    int cnt = 0, first = 0;
    for (int base = 0; base < N; base += 32) {
        int j = base + lane;
        float dx = __fadd_rn(p[3 * j],     -cx);
        float dy = __fadd_rn(p[3 * j + 1], -cy);
        float dz = __fadd_rn(p[3 * j + 2], -cz);
        float d  = __fadd_rn(__fadd_rn(__fmul_rn(dx, dx), __fmul_rn(dy, dy)),
                             __fmul_rn(dz, dz));
        bool hit = d < 0.16f;
        unsigned mask = __ballot_sync(0xffffffffu, hit);
        if (mask) {
            if (cnt == 0) first = base + __ffs(mask) - 1;
            int pos = cnt + __popc(mask & ((1u << lane) - 1u));
            if (hit && pos < NS) outp[pos] = j;
            cnt += __popc(mask);
            if (cnt >= NS) break;
        }
    }
    for (int q = cnt + lane; q < NS; q += 32) outp[q] = first;
}

// ---------------------------------------------------------------------------
// 3) Grouping: build X0 [19][M] (normalized xyz + gathered features)
// ---------------------------------------------------------------------------
__global__ void group_kernel(const float* __restrict__ xyz,
                             const float* __restrict__ feat)
{
    int m = blockIdx.x * blockDim.x + threadIdx.x;
    if (m >= M) return;
    int g = m >> 6;     // / NS
    int b = g >> 10;    // / S
    int j = g_idx[m];
    const float* p = xyz + ((size_t)b * N + j) * 3;
    float cx = g_newxyz[3 * g], cy = g_newxyz[3 * g + 1], cz = g_newxyz[3 * g + 2];
    g_X0[(size_t)0 * M + m] = (p[0] - cx) * 2.5f;
    g_X0[(size_t)1 * M + m] = (p[1] - cy) * 2.5f;
    g_X0[(size_t)2 * M + m] = (p[2] - cz) * 2.5f;
    const float* fb = feat + (size_t)b * C * N + j;
#pragma unroll
    for (int c = 0; c < C; c++)
        g_X0[(size_t)(3 + c) * M + m] = fb[(size_t)c * N];
}

// ---------------------------------------------------------------------------
// 4) 64-output tiled SGEMM with fused input-BN+ReLU, BN partial stats,
//    and (layer 3) fused per-group max.  LAYER selects scratch tensors.
// ---------------------------------------------------------------------------
template<int CIN, int LAYER>
__global__ void __launch_bounds__(256)
gemm64_kernel(const float* __restrict__ Wg, int obase)
{
    constexpr bool NORM   = (LAYER != 1);
    constexpr bool STOREY = (LAYER != 3);
    constexpr bool DOMAX  = (LAYER == 3);

    const float* __restrict__ Xin =
        (LAYER == 1) ? g_X0 : (LAYER == 2) ? g_Y1 : g_Y2;
    const float* __restrict__ scl = (LAYER == 2) ? g_scl1 : g_scl2;
    const float* __restrict__ shf = (LAYER == 2) ? g_shf1 : g_shf2;
    float* __restrict__ Yout = (LAYER == 1) ? g_Y1 : g_Y2;

    __shared__ float Ws[CIN * 64];
    __shared__ float Xs[32 * 128];

    const int tid = threadIdx.x;
    const int m0  = blockIdx.x * 128;
    const int tx  = tid & 15, ty = tid >> 4;

    for (int i = tid; i < CIN * 64; i += 256) {
        int c = i >> 6, o = i & 63;
        Ws[i] = Wg[o * CIN + c];
    }

    float acc[4][8];
#pragma unroll
    for (int i = 0; i < 4; i++)
#pragma unroll
        for (int jj = 0; jj < 8; jj++) acc[i][jj] = 0.f;

    for (int k0 = 0; k0 < CIN; k0 += 32) {
        const int kn = (CIN - k0) < 32 ? (CIN - k0) : 32;
        __syncthreads();
        for (int i = tid; i < kn * 32; i += 256) {
            int r = i >> 5, c4 = i & 31;
            float4 v = *reinterpret_cast<const float4*>(
                Xin + (size_t)(k0 + r) * M + m0 + c4 * 4);
            if (NORM) {
                float sc = scl[k0 + r], sh = shf[k0 + r];
                v.x = fmaxf(fmaf(v.x, sc, sh), 0.f);
                v.y = fmaxf(fmaf(v.y, sc, sh), 0.f);
                v.z = fmaxf(fmaf(v.z, sc, sh), 0.f);
                v.w = fmaxf(fmaf(v.w, sc, sh), 0.f);
            }
            *reinterpret_cast<float4*>(Xs + r * 128 + c4 * 4) = v;
        }
        __syncthreads();
#pragma unroll 4
        for (int k = 0; k < kn; k++) {
            float4 w4 = *reinterpret_cast<const float4*>(Ws + (k0 + k) * 64 + ty * 4);
            float4 xa = *reinterpret_cast<const float4*>(Xs + k * 128 + tx * 8);
            float4 xb = *reinterpret_cast<const float4*>(Xs + k * 128 + tx * 8 + 4);
            float wr[4] = {w4.x, w4.y, w4.z, w4.w};
            float xr[8] = {xa.x, xa.y, xa.z, xa.w, xb.x, xb.y, xb.z, xb.w};
#pragma unroll
            for (int i = 0; i < 4; i++)
#pragma unroll
                for (int jj = 0; jj < 8; jj++)
                    acc[i][jj] = fmaf(wr[i], xr[jj], acc[i][jj]);
        }
    }

    if (STOREY) {
#pragma unroll
        for (int i = 0; i < 4; i++) {
            size_t off = (size_t)(ty * 4 + i) * M + m0 + tx * 8;
            float4 a = make_float4(acc[i][0], acc[i][1], acc[i][2], acc[i][3]);
            float4 q = make_float4(acc[i][4], acc[i][5], acc[i][6], acc[i][7]);
            *reinterpret_cast<float4*>(Yout + off)     = a;
            *reinterpret_cast<float4*>(Yout + off + 4) = q;
        }
    }

    // per-channel partial sum / sumsq (deterministic: fixed shfl order, no atomics)
#pragma unroll
    for (int i = 0; i < 4; i++) {
        float sm = 0.f, sq = 0.f;
#pragma unroll
        for (int jj = 0; jj < 8; jj++) {
            sm += acc[i][jj];
            sq += acc[i][jj] * acc[i][jj];
        }
#pragma unroll
        for (int o = 8; o > 0; o >>= 1) {
            sm += __shfl_xor_sync(0xffffffffu, sm, o);
            sq += __shfl_xor_sync(0xffffffffu, sq, o);
        }
        if (tx == 0) {
            int o = obase + ty * 4 + i;
            g_part[((size_t)o * GB + blockIdx.x) * 2]     = sm;
            g_part[((size_t)o * GB + blockIdx.x) * 2 + 1] = sq;
        }
    }

    if (DOMAX) {
#pragma unroll
        for (int i = 0; i < 4; i++) {
            float mx = acc[i][0];
#pragma unroll
            for (int jj = 1; jj < 8; jj++) mx = fmaxf(mx, acc[i][jj]);
#pragma unroll
            for (int o = 4; o > 0; o >>= 1)
                mx = fmaxf(mx, __shfl_xor_sync(0xffffffffu, mx, o));
            if ((tx & 7) == 0) {
                int grp = (m0 >> 6) + (tx >> 3);
                g_max3[(size_t)(obase + ty * 4 + i) * NG + grp] = mx;
            }
        }
    }
}

// ---------------------------------------------------------------------------
// 5) BN stat finalize (deterministic fixed-order reduction over GB partials)
// ---------------------------------------------------------------------------
template<int LAYER, int COUT>
__global__ void fin_kernel(const float* __restrict__ gam,
                           const float* __restrict__ bet)
{
    float* scl = (LAYER == 1) ? g_scl1 : (LAYER == 2) ? g_scl2 : g_scl3;
    float* shf = (LAYER == 1) ? g_shf1 : (LAYER == 2) ? g_shf2 : g_shf3;
    int o = threadIdx.x;
    if (o >= COUT) return;
    float sm = 0.f, sq = 0.f;
    const float* pp = g_part + (size_t)o * GB * 2;
    for (int i = 0; i < GB; i++) { sm += pp[2 * i]; sq += pp[2 * i + 1]; }
    float mean = sm * (1.0f / (float)M);
    float var  = sq * (1.0f / (float)M) - mean * mean;
    float sc = gam[o] * rsqrtf(var + 1e-5f);
    scl[o] = sc;
    shf[o] = fmaf(-mean, sc, bet[o]);
}

// ---------------------------------------------------------------------------
// 6) Final: normalize+ReLU the group-max, write new_features
// ---------------------------------------------------------------------------
__global__ void out_feat_kernel(float* __restrict__ out)
{
    int idx = blockIdx.x * blockDim.x + threadIdx.x;
    if (idx >= 128 * NG) return;
    int o = idx >> 12;        // / NG
    int g = idx & (NG - 1);
    int b = g >> 10, s = g & 1023;
    float v = fmaxf(fmaf(g_max3[idx], g_scl3[o], g_shf3[o]), 0.f);
    out[OUT_FEAT + ((size_t)(b * 128 + o)) * S + s] = v;
}

// ---------------------------------------------------------------------------
// Launch
// ---------------------------------------------------------------------------
extern "C" void kernel_launch(void* const* d_in, const int* in_sizes, int n_in,
                              void* d_out, int out_size)
{
    (void)in_sizes; (void)n_in; (void)out_size;
    const float* xyz  = (const float*)d_in[0];
    const float* feat = (const float*)d_in[1];
    const float* W1   = (const float*)d_in[2];
    const float* g1   = (const float*)d_in[3];
    const float* b1   = (const float*)d_in[4];
    const float* W2   = (const float*)d_in[5];
    const float* g2   = (const float*)d_in[6];
    const float* b2   = (const float*)d_in[7];
    const float* W3   = (const float*)d_in[8];
    const float* g3   = (const float*)d_in[9];
    const float* b3   = (const float*)d_in[10];
    float* out = (float*)d_out;

    fps_kernel<<<B * CL, FPS_T>>>(xyz, out);
    ball_kernel<<<(NG * 32) / 256, 256>>>(xyz);
    group_kernel<<<M / 256, 256>>>(xyz, feat);

    gemm64_kernel<CIN1, 1><<<GB, 256>>>(W1, 0);
    fin_kernel<1, 64><<<1, 64>>>(g1, b1);

    gemm64_kernel<64, 2><<<GB, 256>>>(W2, 0);
    fin_kernel<2, 64><<<1, 64>>>(g2, b2);

    gemm64_kernel<64, 3><<<GB, 256>>>(W3, 0);
    gemm64_kernel<64, 3><<<GB, 256>>>(W3 + 64 * 64, 64);
    fin_kernel<3, 128><<<1, 128>>>(g3, b3);

    out_feat_kernel<<<(128 * NG) / 256, 256>>>(out);
}